// round 1
// baseline (speedup 1.0000x reference)
#include <cuda_runtime.h>
#include <math.h>

// ---------------- problem constants ----------------
#define S_   2048
#define D_   1024
#define H_   16
#define HD_  64
#define TE_  16
#define TOPK 2
#define ED_  512
#define DS_  2048
#define T_   2048
#define NSLOT (T_*TOPK)
#define EPS_ 1e-5f

// ---------------- scratch (device bss, no allocation) ----------------
__device__ float d_xn[(size_t)T_*D_];          // rmsnorm(x, attn_norm)
__device__ float d_qkv[(size_t)T_*3*D_];       // qkv (rope applied in-place)
__device__ float d_ao[(size_t)T_*D_];          // attention output
__device__ float d_xffn_in[(size_t)T_*D_];     // o-proj + residual
__device__ float d_xffn[(size_t)T_*D_];        // rmsnorm(ffn input)
__device__ float d_scores[NSLOT];
__device__ int   d_counts[TE_];
__device__ int   d_list[TE_*NSLOT];
__device__ float d_g[(size_t)NSLOT*ED_];       // swiglu intermediates per slot
__device__ float d_ys[(size_t)NSLOT*D_];       // per-slot expert outputs
__device__ float d_y[(size_t)T_*D_];           // combined routed output
__device__ float d_up[(size_t)T_*2*DS_];       // shared expert up-proj
__device__ float d_gs[(size_t)T_*DS_];         // shared swiglu
__device__ float d_ysh[(size_t)T_*D_];         // shared expert down-proj

// ---------------- reduction helpers ----------------
__device__ __forceinline__ float block_reduce_sum(float v, float* sh) {
    __syncthreads();
    int lane = threadIdx.x & 31, wid = threadIdx.x >> 5;
#pragma unroll
    for (int o = 16; o; o >>= 1) v += __shfl_xor_sync(0xffffffffu, v, o);
    if (lane == 0) sh[wid] = v;
    __syncthreads();
    int nw = blockDim.x >> 5;
    v = (threadIdx.x < nw) ? sh[threadIdx.x] : 0.f;
    if (wid == 0) {
#pragma unroll
        for (int o = 16; o; o >>= 1) v += __shfl_xor_sync(0xffffffffu, v, o);
        if (lane == 0) sh[0] = v;
    }
    __syncthreads();
    return sh[0];
}

__device__ __forceinline__ float block_reduce_max(float v, float* sh) {
    __syncthreads();
    int lane = threadIdx.x & 31, wid = threadIdx.x >> 5;
#pragma unroll
    for (int o = 16; o; o >>= 1) v = fmaxf(v, __shfl_xor_sync(0xffffffffu, v, o));
    if (lane == 0) sh[wid] = v;
    __syncthreads();
    int nw = blockDim.x >> 5;
    v = (threadIdx.x < nw) ? sh[threadIdx.x] : -1e30f;
    if (wid == 0) {
#pragma unroll
        for (int o = 16; o; o >>= 1) v = fmaxf(v, __shfl_xor_sync(0xffffffffu, v, o));
        if (lane == 0) sh[0] = v;
    }
    __syncthreads();
    return sh[0];
}

// ---------------- rmsnorm ----------------
__global__ void rmsnorm_kernel(const float* __restrict__ x, const float* __restrict__ w,
                               float* __restrict__ out) {
    int row = blockIdx.x;
    const float* xr = x + (size_t)row * D_;
    float ss = 0.f;
    for (int i = threadIdx.x; i < D_; i += blockDim.x) { float v = xr[i]; ss += v * v; }
    __shared__ float sh[32];
    float tot = block_reduce_sum(ss, sh);
    float rinv = rsqrtf(tot / (float)D_ + EPS_);
    float* o = out + (size_t)row * D_;
    for (int i = threadIdx.x; i < D_; i += blockDim.x) o[i] = xr[i] * rinv * w[i];
}

// ---------------- SGEMM: C[M,N] = A[M,K] @ B[N,K]^T (+ optional residual) ----------------
template<int WITH_RES>
__global__ void sgemm_abt(const float* __restrict__ A, const float* __restrict__ Bm,
                          float* __restrict__ C, int M, int N, int Kd,
                          const float* __restrict__ Res) {
    __shared__ float As[16][64];
    __shared__ float Bs[16][64];
    int tid = threadIdx.x;
    int tx = tid & 15, ty = tid >> 4;
    int row0 = blockIdx.y * 64, col0 = blockIdx.x * 64;
    int lm = tid >> 2, lk = (tid & 3) << 2;
    float acc[4][4] = {};
    for (int k0 = 0; k0 < Kd; k0 += 16) {
        float4 a = *(const float4*)(A + (size_t)(row0 + lm) * Kd + k0 + lk);
        float4 b = *(const float4*)(Bm + (size_t)(col0 + lm) * Kd + k0 + lk);
        As[lk + 0][lm] = a.x; As[lk + 1][lm] = a.y; As[lk + 2][lm] = a.z; As[lk + 3][lm] = a.w;
        Bs[lk + 0][lm] = b.x; Bs[lk + 1][lm] = b.y; Bs[lk + 2][lm] = b.z; Bs[lk + 3][lm] = b.w;
        __syncthreads();
#pragma unroll
        for (int k = 0; k < 16; k++) {
            float4 av = ((const float4*)&As[k][0])[ty];
            float4 bv = ((const float4*)&Bs[k][0])[tx];
            float aa[4] = {av.x, av.y, av.z, av.w};
            float bb[4] = {bv.x, bv.y, bv.z, bv.w};
#pragma unroll
            for (int i = 0; i < 4; i++)
#pragma unroll
                for (int j = 0; j < 4; j++) acc[i][j] += aa[i] * bb[j];
        }
        __syncthreads();
    }
#pragma unroll
    for (int i = 0; i < 4; i++) {
        int r = row0 + ty * 4 + i;
#pragma unroll
        for (int j = 0; j < 4; j++) {
            int c = col0 + tx * 4 + j;
            float v = acc[i][j];
            if (WITH_RES) v += Res[(size_t)r * N + c];
            C[(size_t)r * N + c] = v;
        }
    }
}

// ---------------- RoPE (in place on q,k parts of qkv) ----------------
__global__ void rope_kernel(float* __restrict__ qkv) {
    int s = blockIdx.x, h = blockIdx.y, i = threadIdx.x;  // i in [0,32)
    float inv = powf(10000.0f, -(float)i / 32.0f);
    float fr = (float)s * inv;
    float c = cosf(fr), sn = sinf(fr);
    float* q = qkv + (size_t)s * 3 * D_ + h * HD_;
    float* k = q + D_;
    float q1 = q[i], q2 = q[i + 32];
    q[i] = q1 * c + q2 * sn;  q[i + 32] = -q1 * sn + q2 * c;
    float k1 = k[i], k2 = k[i + 32];
    k[i] = k1 * c + k2 * sn;  k[i + 32] = -k1 * sn + k2 * c;
}

// ---------------- attention: one block per (q, head), causal two-pass softmax ----------------
__global__ void attn_kernel(const float* __restrict__ qkv, float* __restrict__ o) {
    int qpos = blockIdx.x, h = blockIdx.y;
    int tid = threadIdx.x;  // 128 threads
    __shared__ float sp[S_];
    __shared__ float qv[HD_];
    __shared__ float red[32];
    __shared__ float oacc[2][HD_];
    const float* qrow = qkv + (size_t)qpos * 3 * D_ + h * HD_;
    if (tid < HD_) qv[tid] = qrow[tid];
    __syncthreads();
    int len = qpos + 1;
    float lmax = -1e30f;
    for (int k = tid; k < len; k += 128) {
        const float* krow = qkv + (size_t)k * 3 * D_ + D_ + h * HD_;
        float s = 0.f;
#pragma unroll
        for (int d = 0; d < HD_; d++) s += qv[d] * krow[d];
        s *= 0.125f;
        sp[k] = s;
        lmax = fmaxf(lmax, s);
    }
    float m = block_reduce_max(lmax, red);
    float lsum = 0.f;
    for (int k = tid; k < len; k += 128) {
        float e = expf(sp[k] - m);
        sp[k] = e;
        lsum += e;
    }
    float tot = block_reduce_sum(lsum, red);
    float inv = 1.0f / tot;
    int d = tid & 63, half = tid >> 6;
    int mid = (len + 1) >> 1;
    int ks = half ? mid : 0, ke = half ? len : mid;
    float acc = 0.f;
    const float* vbase = qkv + 2 * D_ + h * HD_ + d;
    for (int k = ks; k < ke; k++) acc += sp[k] * vbase[(size_t)k * 3 * D_];
    oacc[half][d] = acc;
    __syncthreads();
    if (tid < HD_)
        o[(size_t)qpos * D_ + h * HD_ + tid] = (oacc[0][tid] + oacc[1][tid]) * inv;
}

// ---------------- router ----------------
__global__ void router_kernel(const float* __restrict__ xffn, const float* __restrict__ keys,
                              const int* __restrict__ idx, const float* __restrict__ vals,
                              const float* __restrict__ bias) {
    int t = blockIdx.x, lane = threadIdx.x;  // 32 threads
    int e0 = idx[t * 2], e1 = idx[t * 2 + 1];
    const float* xr = xffn + (size_t)t * D_;
    float s0 = 0.f, s1 = 0.f;
    for (int d = lane; d < D_; d += 32) {
        float x = xr[d];
        s0 += x * keys[d * TE_ + e0];
        s1 += x * keys[d * TE_ + e1];
    }
#pragma unroll
    for (int o = 16; o; o >>= 1) {
        s0 += __shfl_xor_sync(0xffffffffu, s0, o);
        s1 += __shfl_xor_sync(0xffffffffu, s1, o);
    }
    if (lane == 0) {
        float v0 = vals[t * 2] + s0 + bias[e0];
        float v1 = vals[t * 2 + 1] + s1 + bias[e1];
        float mm = fmaxf(v0, v1);
        float a = expf(v0 - mm), b = expf(v1 - mm);
        float inv = 1.0f / (a + b);
        d_scores[t * 2] = a * inv;
        d_scores[t * 2 + 1] = b * inv;
    }
}

// ---------------- expert routing lists ----------------
__global__ void zero_counts_kernel() {
    if (threadIdx.x < TE_) d_counts[threadIdx.x] = 0;
}
__global__ void scatter_kernel(const int* __restrict__ idx) {
    int slot = blockIdx.x * blockDim.x + threadIdx.x;
    if (slot < NSLOT) {
        int e = idx[slot];
        int p = atomicAdd(&d_counts[e], 1);
        d_list[e * NSLOT + p] = slot;
    }
}

// ---------------- expert GEMM1: H1,H2 = Xg @ W1/W2[e]  ([D,ED] row-major), fused SwiGLU ----------------
__global__ void expert_gemm1(const float* __restrict__ xffn, const float* __restrict__ experts) {
    int e = blockIdx.z;
    int cnt = d_counts[e];
    int mt = blockIdx.y;
    if (mt * 64 >= cnt) return;
    __shared__ float As[16][64];
    __shared__ float B1s[16][64];
    __shared__ float B2s[16][64];
    __shared__ int slots[64];
    __shared__ int toks[64];
    int tid = threadIdx.x;
    if (tid < 64) {
        int r = mt * 64 + tid;
        int sl = (r < cnt) ? d_list[e * NSLOT + r] : -1;
        slots[tid] = sl;
        toks[tid] = (sl >= 0) ? sl / TOPK : 0;
    }
    __syncthreads();
    const float* W1 = experts + ((size_t)(0 * TE_ + e)) * D_ * ED_;
    const float* W2 = experts + ((size_t)(1 * TE_ + e)) * D_ * ED_;
    int tx = tid & 15, ty = tid >> 4;
    int lm = tid >> 2, lk = (tid & 3) << 2;      // A gather loader
    int bn4 = (tid & 15) << 2, bk = tid >> 4;    // B loader (row = k, contiguous n)
    int col0 = blockIdx.x * 64;
    float acc1[4][4] = {}, acc2[4][4] = {};
    for (int k0 = 0; k0 < D_; k0 += 16) {
        bool valid = slots[lm] >= 0;
        float4 a = *(const float4*)(xffn + (size_t)toks[lm] * D_ + k0 + lk);
        As[lk + 0][lm] = valid ? a.x : 0.f;
        As[lk + 1][lm] = valid ? a.y : 0.f;
        As[lk + 2][lm] = valid ? a.z : 0.f;
        As[lk + 3][lm] = valid ? a.w : 0.f;
        float4 b1 = *(const float4*)(W1 + (size_t)(k0 + bk) * ED_ + col0 + bn4);
        float4 b2 = *(const float4*)(W2 + (size_t)(k0 + bk) * ED_ + col0 + bn4);
        B1s[bk][bn4 + 0] = b1.x; B1s[bk][bn4 + 1] = b1.y; B1s[bk][bn4 + 2] = b1.z; B1s[bk][bn4 + 3] = b1.w;
        B2s[bk][bn4 + 0] = b2.x; B2s[bk][bn4 + 1] = b2.y; B2s[bk][bn4 + 2] = b2.z; B2s[bk][bn4 + 3] = b2.w;
        __syncthreads();
#pragma unroll
        for (int k = 0; k < 16; k++) {
            float4 av = ((const float4*)&As[k][0])[ty];
            float4 b1v = ((const float4*)&B1s[k][0])[tx];
            float4 b2v = ((const float4*)&B2s[k][0])[tx];
            float aa[4] = {av.x, av.y, av.z, av.w};
            float p[4] = {b1v.x, b1v.y, b1v.z, b1v.w};
            float q[4] = {b2v.x, b2v.y, b2v.z, b2v.w};
#pragma unroll
            for (int i = 0; i < 4; i++)
#pragma unroll
                for (int j = 0; j < 4; j++) {
                    acc1[i][j] += aa[i] * p[j];
                    acc2[i][j] += aa[i] * q[j];
                }
        }
        __syncthreads();
    }
#pragma unroll
    for (int i = 0; i < 4; i++) {
        int sl = slots[ty * 4 + i];
        if (sl < 0) continue;
#pragma unroll
        for (int j = 0; j < 4; j++) {
            float h1 = acc1[i][j], h2 = acc2[i][j];
            float g = (h1 / (1.f + expf(-h1))) * h2;
            d_g[(size_t)sl * ED_ + col0 + tx * 4 + j] = g;
        }
    }
}

// ---------------- expert GEMM2: Ys = G @ W3[e]^T  (W3 [D,ED] row-major) ----------------
__global__ void expert_gemm2(const float* __restrict__ experts) {
    int e = blockIdx.z;
    int cnt = d_counts[e];
    int mt = blockIdx.y;
    if (mt * 64 >= cnt) return;
    __shared__ float As[16][64];
    __shared__ float Bs[16][64];
    __shared__ int slots[64];
    int tid = threadIdx.x;
    if (tid < 64) {
        int r = mt * 64 + tid;
        slots[tid] = (r < cnt) ? d_list[e * NSLOT + r] : -1;
    }
    __syncthreads();
    const float* W3 = experts + ((size_t)(2 * TE_ + e)) * D_ * ED_;
    int tx = tid & 15, ty = tid >> 4;
    int lm = tid >> 2, lk = (tid & 3) << 2;
    int col0 = blockIdx.x * 64;
    float acc[4][4] = {};
    for (int k0 = 0; k0 < ED_; k0 += 16) {
        int sl = slots[lm];
        bool valid = sl >= 0;
        float4 a = *(const float4*)(d_g + (size_t)(valid ? sl : 0) * ED_ + k0 + lk);
        As[lk + 0][lm] = valid ? a.x : 0.f;
        As[lk + 1][lm] = valid ? a.y : 0.f;
        As[lk + 2][lm] = valid ? a.z : 0.f;
        As[lk + 3][lm] = valid ? a.w : 0.f;
        float4 b = *(const float4*)(W3 + (size_t)(col0 + lm) * ED_ + k0 + lk);
        Bs[lk + 0][lm] = b.x; Bs[lk + 1][lm] = b.y; Bs[lk + 2][lm] = b.z; Bs[lk + 3][lm] = b.w;
        __syncthreads();
#pragma unroll
        for (int k = 0; k < 16; k++) {
            float4 av = ((const float4*)&As[k][0])[ty];
            float4 bv = ((const float4*)&Bs[k][0])[tx];
            float aa[4] = {av.x, av.y, av.z, av.w};
            float bb[4] = {bv.x, bv.y, bv.z, bv.w};
#pragma unroll
            for (int i = 0; i < 4; i++)
#pragma unroll
                for (int j = 0; j < 4; j++) acc[i][j] += aa[i] * bb[j];
        }
        __syncthreads();
    }
#pragma unroll
    for (int i = 0; i < 4; i++) {
        int sl = slots[ty * 4 + i];
        if (sl < 0) continue;
#pragma unroll
        for (int j = 0; j < 4; j++)
            d_ys[(size_t)sl * D_ + col0 + tx * 4 + j] = acc[i][j];
    }
}

// ---------------- combine routed outputs (scores + output_coeff) ----------------
__global__ void combine_kernel(const float* __restrict__ coeff) {
    int t = blockIdx.x, tid = threadIdx.x;
    float s0 = d_scores[t * 2], s1 = d_scores[t * 2 + 1];
    const float* y0 = d_ys + (size_t)(t * 2) * D_;
    const float* y1 = d_ys + (size_t)(t * 2 + 1) * D_;
    float* yo = d_y + (size_t)t * D_;
    for (int dd = tid; dd < D_; dd += 256)
        yo[dd] = (s0 * y0[dd] + s1 * y1[dd]) * coeff[dd];
}

// ---------------- shared expert swiglu ----------------
__global__ void swiglu_shared_kernel() {
    size_t i = (size_t)blockIdx.x * blockDim.x + threadIdx.x;
    if (i < (size_t)T_ * DS_) {
        size_t t = i / DS_, hh = i % DS_;
        float a = d_up[t * 2 * DS_ + hh];
        float b = d_up[t * 2 * DS_ + DS_ + hh];
        d_gs[i] = (a / (1.f + expf(-a))) * b;
    }
}

// ---------------- final: rmsnorm(shared) + add everything ----------------
__global__ void final_kernel(const float* __restrict__ sharedw, float* __restrict__ out) {
    int t = blockIdx.x;
    const float* ysh = d_ysh + (size_t)t * D_;
    float ss = 0.f;
    for (int i = threadIdx.x; i < D_; i += blockDim.x) { float v = ysh[i]; ss += v * v; }
    __shared__ float sh[32];
    float tot = block_reduce_sum(ss, sh);
    float rinv = rsqrtf(tot / (float)D_ + EPS_);
    const float* yr = d_y + (size_t)t * D_;
    const float* xr = d_xffn_in + (size_t)t * D_;
    float* o = out + (size_t)t * D_;
    for (int i = threadIdx.x; i < D_; i += blockDim.x)
        o[i] = yr[i] + ysh[i] * rinv * sharedw[i] + xr[i];
}

// ---------------- host launch ----------------
static float* symf(const void* sym) { void* p = nullptr; cudaGetSymbolAddress(&p, sym); return (float*)p; }

extern "C" void kernel_launch(void* const* d_in, const int* in_sizes, int n_in,
                              void* d_out, int out_size) {
    const float* x_input      = (const float*)d_in[0];
    const int*   indices      = (const int*)  d_in[1];
    const float* values       = (const float*)d_in[2];
    const float* attn_w       = (const float*)d_in[3];
    const float* attn_o_w     = (const float*)d_in[4];
    const float* attn_norm_w  = (const float*)d_in[5];
    const float* ffn_norm_w   = (const float*)d_in[6];
    const float* ffn_experts  = (const float*)d_in[7];
    const float* main_keys    = (const float*)d_in[8];
    const float* main_bias    = (const float*)d_in[9];
    const float* output_coeff = (const float*)d_in[10];
    const float* ffn_up_w     = (const float*)d_in[11];
    const float* ffn_down_w   = (const float*)d_in[12];
    const float* shared_norm_w= (const float*)d_in[13];
    float* out = (float*)d_out;

    float* p_xn      = symf(d_xn);
    float* p_qkv     = symf(d_qkv);
    float* p_ao      = symf(d_ao);
    float* p_xffn_in = symf(d_xffn_in);
    float* p_xffn    = symf(d_xffn);
    float* p_up      = symf(d_up);
    float* p_gs      = symf(d_gs);
    float* p_ysh     = symf(d_ysh);

    // attention block
    rmsnorm_kernel<<<T_, 256>>>(x_input, attn_norm_w, p_xn);
    sgemm_abt<0><<<dim3(3 * D_ / 64, T_ / 64), 256>>>(p_xn, attn_w, p_qkv, T_, 3 * D_, D_, nullptr);
    rope_kernel<<<dim3(S_, H_), 32>>>(p_qkv);
    attn_kernel<<<dim3(S_, H_), 128>>>(p_qkv, p_ao);
    sgemm_abt<1><<<dim3(D_ / 64, T_ / 64), 256>>>(p_ao, attn_o_w, p_xffn_in, T_, D_, D_, x_input);

    // ffn norm + router
    rmsnorm_kernel<<<T_, 256>>>(p_xffn_in, ffn_norm_w, p_xffn);
    router_kernel<<<T_, 32>>>(p_xffn, main_keys, indices, values, main_bias);
    zero_counts_kernel<<<1, 32>>>();
    scatter_kernel<<<(NSLOT + 255) / 256, 256>>>(indices);

    // routed experts (grouped, gathered)
    expert_gemm1<<<dim3(ED_ / 64, NSLOT / 64, TE_), 256>>>(p_xffn, ffn_experts);
    expert_gemm2<<<dim3(D_ / 64, NSLOT / 64, TE_), 256>>>(ffn_experts);
    combine_kernel<<<T_, 256>>>(output_coeff);

    // shared expert
    sgemm_abt<0><<<dim3(2 * DS_ / 64, T_ / 64), 256>>>(p_xffn, ffn_up_w, p_up, T_, 2 * DS_, D_, nullptr);
    swiglu_shared_kernel<<<((size_t)T_ * DS_ + 255) / 256, 256>>>();
    sgemm_abt<0><<<dim3(D_ / 64, T_ / 64), 256>>>(p_gs, ffn_down_w, p_ysh, T_, D_, DS_, nullptr);

    // final combine
    final_kernel<<<T_, 256>>>(shared_norm_w, out);
}